// round 12
// baseline (speedup 1.0000x reference)
#include <cuda_runtime.h>
#include <cuda_fp16.h>

// R12: single fused kernel. Builder CTAs (bid<1024) construct the fp16 quad
// table, then everyone interpolates; consumers overlap their streaming
// prologue with the build and sync on a device flag (release/acquire).
//   d_in[0] = points [N,2] fp32, d_in[1] = grid [1024,1024] fp32,
//   d_in[2] = bounds [2,2] fp32, d_out = [N] fp32

#define GRID_W 1024
#define GRID_H 1024
#define QUAD_ROWS   (GRID_H - 1)

#define THREADS        128
#define N_BUILD_CTAS   1024
#define BUILD_ITEMS    (QUAD_ROWS * (GRID_W / 4))          // 261,888 (4 quads each)
#define BUILD_THREADS  (N_BUILD_CTAS * THREADS)            // 131,072 -> 2 items/thread

// quad[y*1024 + x] = half2(tl,tr), half2(bl,br) -> uint2, 8.4 MB
__device__ uint2 g_quad[QUAD_ROWS * 1024];
__device__ unsigned int g_done;   // reset to 0 by cudaMemsetAsync every launch

__device__ __forceinline__ void build_item(const float* __restrict__ grid, int t) {
    if (t >= BUILD_ITEMS) return;
    int y  = t >> 8;            // row 0..1022
    int xb = (t & 255) << 2;    // x block start: 0,4,...,1020

    const float* r0 = grid + (y << 10) + xb;
    const float* r1 = r0 + GRID_W;

    float4 a0 = *reinterpret_cast<const float4*>(r0);
    float4 a1 = *reinterpret_cast<const float4*>(r1);
    int noff = (xb == GRID_W - 4) ? 3 : 4;   // quad at x=1023 never gathered
    float e0 = r0[noff];
    float e1 = r1[noff];

    float t0[5] = {a0.x, a0.y, a0.z, a0.w, e0};
    float b0[5] = {a1.x, a1.y, a1.z, a1.w, e1};

    uint2 q[4];
#pragma unroll
    for (int k = 0; k < 4; k++) {
        __half2 top = __floats2half2_rn(t0[k], t0[k + 1]);
        __half2 bot = __floats2half2_rn(b0[k], b0[k + 1]);
        q[k].x = *reinterpret_cast<unsigned int*>(&top);
        q[k].y = *reinterpret_cast<unsigned int*>(&bot);
    }

    uint2* dst = &g_quad[(y << 10) + xb];
    reinterpret_cast<uint4*>(dst)[0] = make_uint4(q[0].x, q[0].y, q[1].x, q[1].y);
    reinterpret_cast<uint4*>(dst)[1] = make_uint4(q[2].x, q[2].y, q[3].x, q[3].y);
}

__device__ __forceinline__ unsigned int ld_acquire(const unsigned int* p) {
    unsigned int v;
    asm volatile("ld.acquire.gpu.global.u32 %0, [%1];" : "=r"(v) : "l"(p) : "memory");
    return v;
}

__global__ __launch_bounds__(THREADS, 16)
void fused_kernel(const float4* __restrict__ pts,
                  const float* __restrict__ grid,
                  const float* __restrict__ bounds,
                  float* __restrict__ out,
                  int n_quads) {
    int bid = blockIdx.x;
    int i = bid * THREADS + threadIdx.x;

    // ---- Builder phase (CTAs 0..1023) ----
    if (bid < N_BUILD_CTAS) {
        int t = bid * THREADS + threadIdx.x;
        build_item(grid, t);
        build_item(grid, t + BUILD_THREADS);
        __threadfence();                       // release table writes
        __syncthreads();                       // whole CTA's writes done
        if (threadIdx.x == 0) atomicAdd(&g_done, 1u);
    }

    // ---- Prologue: table-independent work (overlaps the build) ----
    float x_lo = __ldg(bounds + 0);
    float x_hi = __ldg(bounds + 1);
    float v_lo = __ldg(bounds + 2);
    float v_hi = __ldg(bounds + 3);
    float sy = (float)(GRID_H - 1) / (x_hi - x_lo);
    float sx = (float)(GRID_W - 1) / (v_hi - v_lo);

    float4 p01 = __ldcs(&pts[2 * i]);
    float4 p23 = __ldcs(&pts[2 * i + 1]);

    float px[4] = {p01.x, p01.z, p23.x, p23.z};
    float pv[4] = {p01.y, p01.w, p23.y, p23.w};

    int   idx[4];
    float ax[4], ay[4];
#pragma unroll
    for (int k = 0; k < 4; k++) {
        float qy = (px[k] - x_lo) * sy;
        float qx = (pv[k] - v_lo) * sx;
        float fy = fminf(fmaxf(floorf(qy), 0.0f), (float)(GRID_H - 2));
        float fx = fminf(fmaxf(floorf(qx), 0.0f), (float)(GRID_W - 2));
        ay[k] = fminf(fmaxf(qy - fy, 0.0f), 1.0f);
        ax[k] = fminf(fmaxf(qx - fx, 0.0f), 1.0f);
        idx[k] = (((int)fy) << 10) + (int)fx;
    }

    // ---- Wait for the table (thread0 spins; all threads acquire) ----
    if (threadIdx.x == 0) {
        while (ld_acquire(&g_done) != (unsigned)N_BUILD_CTAS) __nanosleep(64);
    }
    __syncthreads();
    (void)ld_acquire(&g_done);   // per-thread acquire: orders table reads below

    // ---- Gather + blend + store ----
    uint2 q[4];
#pragma unroll
    for (int k = 0; k < 4; k++) q[k] = __ldg(&g_quad[idx[k]]);

    float r[4];
#pragma unroll
    for (int k = 0; k < 4; k++) {
        float2 t = __half22float2(*reinterpret_cast<const __half2*>(&q[k].x)); // tl,tr
        float2 b = __half22float2(*reinterpret_cast<const __half2*>(&q[k].y)); // bl,br
        float top = fmaf(t.y - t.x, ax[k], t.x);
        float bot = fmaf(b.y - b.x, ax[k], b.x);
        r[k] = fmaf(bot - top, ay[k], top);
    }

    __stcs(reinterpret_cast<float4*>(out) + i, make_float4(r[0], r[1], r[2], r[3]));
}

extern "C" void kernel_launch(void* const* d_in, const int* in_sizes, int n_in,
                              void* d_out, int out_size) {
    const float4* pts  = (const float4*)d_in[0];
    const float*  grid = (const float*)d_in[1];
    const float*  bnds = (const float*)d_in[2];
    float*        out  = (float*)d_out;

    // Reset the completion flag (capture-legal memset node, no allocation).
    void* done_ptr = nullptr;
    cudaGetSymbolAddress(&done_ptr, g_done);
    cudaMemsetAsync(done_ptr, 0, sizeof(unsigned int));

    int n = in_sizes[0] / 2;   // number of points ([N,2])
    int n_quads = n / 4;       // 1,048,576 = 8192 * 128 (exact)

    int blocks = n_quads / THREADS;   // 8192
    fused_kernel<<<blocks, THREADS>>>(pts, grid, bnds, out, n_quads);
}